// round 2
// baseline (speedup 1.0000x reference)
#include <cuda_runtime.h>
#include <cuda_bf16.h>

#define SEQ   4096
#define EMBED 256
#define NQ    8
#define TAGS  50
#define DIN   264   // EMBED + NQ

// Scratch (device globals — no dynamic allocation allowed)
__device__ float g_ax[SEQ * 32];   // [t][gate][q] pre-activations from x_t (+bias)
__device__ float g_h[SEQ * NQ];    // lstm hidden outputs

// ---------------------------------------------------------------------------
// Kernel 1: ax[t][g][q] = W_g[q, :256] @ emb[sentence[t]] + b_g[q]
// One block per timestep, 256 threads. 8 threads cooperate per (g,q) output.
// ---------------------------------------------------------------------------
__global__ void precompute_kernel(const int* __restrict__ sent,
                                  const float* __restrict__ emb,
                                  const float* __restrict__ Wf, const float* __restrict__ bf,
                                  const float* __restrict__ Wi, const float* __restrict__ bi,
                                  const float* __restrict__ Wu, const float* __restrict__ bu,
                                  const float* __restrict__ Wo, const float* __restrict__ bo) {
    __shared__ float xe[EMBED];
    const int t   = blockIdx.x;
    const int tid = threadIdx.x;
    const int s   = sent[t];
    xe[tid] = emb[(size_t)s * EMBED + tid];
    __syncthreads();

    const int outi = tid >> 3;      // 0..31 : gate*8 + q
    const int g    = outi >> 3;     // 0..3
    const int q    = outi & 7;
    const int sub  = tid & 7;       // 0..7 within the reduction group

    const float* W = (g == 0) ? Wf : (g == 1) ? Wi : (g == 2) ? Wu : Wo;
    const float* b = (g == 0) ? bf : (g == 1) ? bi : (g == 2) ? bu : bo;
    const float* row = W + q * DIN;

    float acc = 0.f;
#pragma unroll
    for (int j = 0; j < 32; j++)
        acc = fmaf(row[sub * 32 + j], xe[sub * 32 + j], acc);

    // reduce across the 8-lane group (groups are lane-aligned within the warp)
    acc += __shfl_xor_sync(0xffffffffu, acc, 4);
    acc += __shfl_xor_sync(0xffffffffu, acc, 2);
    acc += __shfl_xor_sync(0xffffffffu, acc, 1);

    if (sub == 0)
        g_ax[t * 32 + outi] = acc + b[q];
}

// ---------------------------------------------------------------------------
// Kernel 2: the sequential LSTM scan. Single warp. lane = gate*8 + q.
// The quantum layer reduces analytically to:
//   z_j = prod_{k<=j} cos^2(a_k)  (j>=1);   z_0 = prod_{k=1..7} cos^2(a_k)
// ---------------------------------------------------------------------------
__global__ void scan_kernel(const float* __restrict__ Wf, const float* __restrict__ Wi,
                            const float* __restrict__ Wu, const float* __restrict__ Wo) {
    const unsigned FULL = 0xffffffffu;
    const int lane = threadIdx.x;          // 0..31
    const int g = lane >> 3, q = lane & 7;
    const int base = g << 3;

    const float* W = (g == 0) ? Wf : (g == 1) ? Wi : (g == 2) ? Wu : Wo;
    float w[NQ];
#pragma unroll
    for (int k = 0; k < NQ; k++)
        w[k] = W[q * DIN + EMBED + k];     // recurrent slice W[:, 256:264]

    // unified activation: act = mscale * (1/(1+exp(escale*x))) + offs
    //   sigmoid(x) = 1/(1+e^-x)      -> escale=-1, mscale=1, offs=0
    //   tanh(x)    = 2/(1+e^-2x) - 1 -> escale=-2, mscale=2, offs=-1
    const float escale = (g == 2) ? -2.f : -1.f;
    const float mscale = (g == 2) ?  2.f :  1.f;
    const float offs   = (g == 2) ? -1.f :  0.f;

    float hx = 0.f, cx = 0.f;
    // 2-deep prefetch of ax
    float a0 = g_ax[lane];
    float a1 = g_ax[32 + lane];

    for (int t = 0; t < SEQ; t++) {
        const float a = a0;
        a0 = a1;
        if (t + 2 < SEQ) a1 = g_ax[(t + 2) * 32 + lane];

        // angle = a + Wh[q,:] @ hx  (hx replicated: lane k holds hx[k])
        float acc0 = a, acc1 = 0.f;
#pragma unroll
        for (int k = 0; k < NQ; k += 2) {
            acc0 = fmaf(w[k],     __shfl_sync(FULL, hx, k),     acc0);
            acc1 = fmaf(w[k + 1], __shfl_sync(FULL, hx, k + 1), acc1);
        }
        const float ang = acc0 + acc1;

        float cc = __cosf(ang);
        cc = cc * cc;

        // gather all 8 cos^2 of my gate group; select-product tree
        float m[NQ];
#pragma unroll
        for (int k = 0; k < NQ; k++) {
            const float v = __shfl_sync(FULL, cc, base + k);
            const bool inc = (k == 0) ? (q != 0) : ((q == 0) || (k <= q));
            m[k] = inc ? v : 1.0f;
        }
        const float p = ((m[0] * m[1]) * (m[2] * m[3])) *
                        ((m[4] * m[5]) * (m[6] * m[7]));

        // activation
        const float e = __expf(p * escale);
        const float r = __fdividef(1.0f, 1.0f + e);
        const float act = fmaf(mscale, r, offs);

        // gather f,i,g,o for my q (every lane keeps a replicated copy)
        const float fg = __shfl_sync(FULL, act, q);
        const float ig = __shfl_sync(FULL, act, 8 + q);
        const float gg = __shfl_sync(FULL, act, 16 + q);
        const float og = __shfl_sync(FULL, act, 24 + q);

        cx = fmaf(fg, cx, ig * gg);
        const float e2 = __expf(-2.0f * cx);
        const float th = fmaf(2.0f, __fdividef(1.0f, 1.0f + e2), -1.0f);
        hx = og * th;

        if (lane < NQ)
            g_h[t * NQ + lane] = hx;
    }
}

// ---------------------------------------------------------------------------
// Kernel 3: logits = h @ Wt^T + bt, then log_softmax over 50 tags.
// One block (32 threads) per timestep; lane handles tags {lane, lane+32}.
// ---------------------------------------------------------------------------
__global__ void logits_kernel(const float* __restrict__ Wt, const float* __restrict__ bt,
                              float* __restrict__ out) {
    const unsigned FULL = 0xffffffffu;
    const int t = blockIdx.x;
    const int lane = threadIdx.x;

    float h[NQ];
#pragma unroll
    for (int k = 0; k < NQ; k++)
        h[k] = g_h[t * NQ + k];

    // tag0 = lane (always < 50), tag1 = lane + 32 (valid if < 50)
    float l0 = bt[lane];
#pragma unroll
    for (int k = 0; k < NQ; k++)
        l0 = fmaf(Wt[lane * NQ + k], h[k], l0);

    const int tag1 = lane + 32;
    const bool v1 = (tag1 < TAGS);
    float l1 = -3.0e38f;
    if (v1) {
        l1 = bt[tag1];
#pragma unroll
        for (int k = 0; k < NQ; k++)
            l1 = fmaf(Wt[tag1 * NQ + k], h[k], l1);
    }

    float mx = fmaxf(l0, l1);
#pragma unroll
    for (int d = 16; d; d >>= 1)
        mx = fmaxf(mx, __shfl_xor_sync(FULL, mx, d));

    float se = expf(l0 - mx) + (v1 ? expf(l1 - mx) : 0.f);
#pragma unroll
    for (int d = 16; d; d >>= 1)
        se += __shfl_xor_sync(FULL, se, d);

    const float ls = mx + logf(se);
    out[t * TAGS + lane] = l0 - ls;
    if (v1)
        out[t * TAGS + tag1] = l1 - ls;
}

// ---------------------------------------------------------------------------
extern "C" void kernel_launch(void* const* d_in, const int* in_sizes, int n_in,
                              void* d_out, int out_size) {
    const int*   sent = (const int*)  d_in[0];
    const float* emb  = (const float*)d_in[1];
    const float* Wf   = (const float*)d_in[2];
    const float* bf   = (const float*)d_in[3];
    const float* Wi   = (const float*)d_in[4];
    const float* bi   = (const float*)d_in[5];
    const float* Wu   = (const float*)d_in[6];
    const float* bu   = (const float*)d_in[7];
    const float* Wo   = (const float*)d_in[8];
    const float* bo   = (const float*)d_in[9];
    const float* Wt   = (const float*)d_in[10];
    const float* bt   = (const float*)d_in[11];
    float* out = (float*)d_out;

    precompute_kernel<<<SEQ, 256>>>(sent, emb, Wf, bf, Wi, bi, Wu, bu, Wo, bo);
    scan_kernel<<<1, 32>>>(Wf, Wi, Wu, Wo);
    logits_kernel<<<SEQ, 32>>>(Wt, bt, out);
}

// round 3
// speedup vs baseline: 1.0716x; 1.0716x over previous
#include <cuda_runtime.h>
#include <cuda_bf16.h>

#define SEQ   4096
#define EMBED 256
#define NQ    8
#define TAGS  50
#define DIN   264   // EMBED + NQ
#define TCHUNK 16   // timesteps per precompute block

// Scratch (device globals — no dynamic allocation allowed)
__device__ float g_ax[SEQ * 32];   // [t][gate][q] pre-activations from x_t (+bias)
__device__ float g_h[SEQ * NQ];    // lstm hidden outputs

// ---------------------------------------------------------------------------
// Kernel 1: ax[t][g][q] = W_g[q, :256] @ emb[sentence[t]] + b_g[q]
// 256 blocks x 16 timesteps. Weights in registers (32/thread), embedding row
// double-buffered in padded (conflict-free) smem. 8 threads per (g,q) output.
// ---------------------------------------------------------------------------
__global__ void __launch_bounds__(256) precompute_kernel(
        const int* __restrict__ sent, const float* __restrict__ emb,
        const float* __restrict__ Wf, const float* __restrict__ bf,
        const float* __restrict__ Wi, const float* __restrict__ bi,
        const float* __restrict__ Wu, const float* __restrict__ bu,
        const float* __restrict__ Wo, const float* __restrict__ bo) {
    __shared__ float xe[2][264];               // 256 elems padded: idx + (idx>>5)

    const int tid  = threadIdx.x;
    const int t0   = blockIdx.x * TCHUNK;
    const int outi = tid >> 3;                 // 0..31 : gate*8 + q
    const int g    = outi >> 3;
    const int q    = outi & 7;
    const int sub  = tid & 7;

    const float* W = (g == 0) ? Wf : (g == 1) ? Wi : (g == 2) ? Wu : Wo;
    const float* b = (g == 0) ? bf : (g == 1) ? bi : (g == 2) ? bu : bo;

    // weights for my 32-element slice of the dot product -> registers
    float wreg[32];
    const float* row = W + q * DIN + sub * 32;
#pragma unroll
    for (int j = 0; j < 32; j++) wreg[j] = row[j];
    const float bias = b[q];

    // preload first embedding row
    {
        const int s = sent[t0];
        xe[0][tid + (tid >> 5)] = emb[(size_t)s * EMBED + tid];
    }
    __syncthreads();

    const int pbase = sub * 33;                // padded base for reads

    for (int i = 0; i < TCHUNK; i++) {
        const int buf = i & 1;
        const int t   = t0 + i;

        float nxt = 0.f;
        if (i + 1 < TCHUNK) {
            const int s2 = sent[t + 1];
            nxt = emb[(size_t)s2 * EMBED + tid];
        }

        float acc = 0.f;
#pragma unroll
        for (int j = 0; j < 32; j++)
            acc = fmaf(wreg[j], xe[buf][pbase + j], acc);

        acc += __shfl_xor_sync(0xffffffffu, acc, 4);
        acc += __shfl_xor_sync(0xffffffffu, acc, 2);
        acc += __shfl_xor_sync(0xffffffffu, acc, 1);

        if (sub == 0)
            g_ax[t * 32 + outi] = acc + bias;

        if (i + 1 < TCHUNK)
            xe[buf ^ 1][tid + (tid >> 5)] = nxt;
        __syncthreads();
    }
}

// ---------------------------------------------------------------------------
// Kernel 2: the sequential LSTM scan. Single warp. lane = gate*8 + q.
// Quantum layer collapses analytically:
//   z_j = prod_{k<=j} cos^2(a_k)  (j>=1);   z_0 = prod_{k=1..7} cos^2(a_k)
// Activations via Pade(9) tanh:  tanh(x) = x(945+105t+t^2)/(945+420t+15t^2)
//   sigmoid(p) = 0.5 + 0.5*tanh(p/2): with u=p^2 ->
//     0.5 + 0.25*p*(15120+420u+u^2)/(15120+1680u+15u^2)
// ---------------------------------------------------------------------------
__global__ void __launch_bounds__(32, 1) scan_kernel(
        const float* __restrict__ Wf, const float* __restrict__ Wi,
        const float* __restrict__ Wu, const float* __restrict__ Wo) {
    const unsigned FULL = 0xffffffffu;
    const int lane = threadIdx.x;          // 0..31
    const int g = lane >> 3, q = lane & 7;
    const int base = g << 3;

    const float* W = (g == 0) ? Wf : (g == 1) ? Wi : (g == 2) ? Wu : Wo;
    float w[NQ];
#pragma unroll
    for (int k = 0; k < NQ; k++)
        w[k] = W[q * DIN + EMBED + k];     // recurrent slice W[:, 256:264]

    // per-lane Pade coefficients (n2 = 1 in both cases)
    float n0, n1, d0, d1, M, C;
    const float d2 = 15.f;
    if (g == 2) { n0 = 945.f;   n1 = 105.f; d0 = 945.f;   d1 = 420.f;  M = 1.f;   C = 0.f;  }
    else        { n0 = 15120.f; n1 = 420.f; d0 = 15120.f; d1 = 1680.f; M = 0.25f; C = 0.5f; }

    bool inc[NQ];
#pragma unroll
    for (int k = 0; k < NQ; k++)
        inc[k] = (k == 0) ? (q != 0) : ((q == 0) || (k <= q));

    float hx = 0.f, cx = 0.f;
    float a0 = g_ax[lane];
    float a1 = g_ax[32 + lane];

#pragma unroll 2
    for (int t = 0; t < SEQ; t++) {
        const float a = a0;
        a0 = a1;
        const int tn = (t + 2 < SEQ) ? (t + 2) : (SEQ - 1);
        a1 = g_ax[tn * 32 + lane];

        // ---- stage A: broadcast hx, recurrent matvec ----
        const float h0 = __shfl_sync(FULL, hx, 0);
        const float h1 = __shfl_sync(FULL, hx, 1);
        const float h2 = __shfl_sync(FULL, hx, 2);
        const float h3 = __shfl_sync(FULL, hx, 3);
        const float h4 = __shfl_sync(FULL, hx, 4);
        const float h5 = __shfl_sync(FULL, hx, 5);
        const float h6 = __shfl_sync(FULL, hx, 6);
        const float h7 = __shfl_sync(FULL, hx, 7);

        float c0 = fmaf(w[1], h1, fmaf(w[0], h0, a));
        float c1 = fmaf(w[3], h3, w[2] * h2);
        float c2 = fmaf(w[5], h5, w[4] * h4);
        float c3 = fmaf(w[7], h7, w[6] * h6);
        const float ang = (c0 + c1) + (c2 + c3);

        float cc = __cosf(ang);
        cc = cc * cc;

        // ---- stage B: gather cos^2, masked product ----
        float m[NQ];
#pragma unroll
        for (int k = 0; k < NQ; k++) {
            const float v = __shfl_sync(FULL, cc, base + k);
            m[k] = inc[k] ? v : 1.0f;
        }
        const float p = ((m[0] * m[1]) * (m[2] * m[3])) *
                        ((m[4] * m[5]) * (m[6] * m[7]));

        // ---- activation: act = C + M*p * num(u)/den(u), u = p^2 ----
        const float u   = p * p;
        const float num = fmaf(u + n1, u, n0);
        const float den = fmaf(fmaf(d2, u, d1), u, d0);
        const float Mp  = M * p;
        const float act = fmaf(Mp, __fdividef(num, den), C);

        // ---- stage C: gather f,i,g,o for my wire ----
        const float fg = __shfl_sync(FULL, act, q);
        const float ig = __shfl_sync(FULL, act, 8 + q);
        const float gg = __shfl_sync(FULL, act, 16 + q);
        const float og = __shfl_sync(FULL, act, 24 + q);

        cx = fmaf(fg, cx, ig * gg);

        // hx = og * tanh(cx) via Pade: (og*cx*numc) * rcp(denc)
        const float tc   = cx * cx;
        const float numc = fmaf(tc + 105.f, tc, 945.f);
        const float denc = fmaf(fmaf(15.f, tc, 420.f), tc, 945.f);
        const float ocn  = (og * cx) * numc;
        hx = ocn * __fdividef(1.0f, denc);

        if (lane < NQ)
            g_h[t * NQ + lane] = hx;
    }
}

// ---------------------------------------------------------------------------
// Kernel 3: logits = h @ Wt^T + bt, then log_softmax over 50 tags.
// One block (32 threads) per timestep; lane handles tags {lane, lane+32}.
// ---------------------------------------------------------------------------
__global__ void logits_kernel(const float* __restrict__ Wt, const float* __restrict__ bt,
                              float* __restrict__ out) {
    const unsigned FULL = 0xffffffffu;
    const int t = blockIdx.x;
    const int lane = threadIdx.x;

    float h[NQ];
#pragma unroll
    for (int k = 0; k < NQ; k++)
        h[k] = g_h[t * NQ + k];

    float l0 = bt[lane];
#pragma unroll
    for (int k = 0; k < NQ; k++)
        l0 = fmaf(Wt[lane * NQ + k], h[k], l0);

    const int tag1 = lane + 32;
    const bool v1 = (tag1 < TAGS);
    float l1 = -3.0e38f;
    if (v1) {
        l1 = bt[tag1];
#pragma unroll
        for (int k = 0; k < NQ; k++)
            l1 = fmaf(Wt[tag1 * NQ + k], h[k], l1);
    }

    float mx = fmaxf(l0, l1);
#pragma unroll
    for (int d = 16; d; d >>= 1)
        mx = fmaxf(mx, __shfl_xor_sync(FULL, mx, d));

    float se = expf(l0 - mx) + (v1 ? expf(l1 - mx) : 0.f);
#pragma unroll
    for (int d = 16; d; d >>= 1)
        se += __shfl_xor_sync(FULL, se, d);

    const float ls = mx + logf(se);
    out[t * TAGS + lane] = l0 - ls;
    if (v1)
        out[t * TAGS + tag1] = l1 - ls;
}

// ---------------------------------------------------------------------------
extern "C" void kernel_launch(void* const* d_in, const int* in_sizes, int n_in,
                              void* d_out, int out_size) {
    const int*   sent = (const int*)  d_in[0];
    const float* emb  = (const float*)d_in[1];
    const float* Wf   = (const float*)d_in[2];
    const float* bf   = (const float*)d_in[3];
    const float* Wi   = (const float*)d_in[4];
    const float* bi   = (const float*)d_in[5];
    const float* Wu   = (const float*)d_in[6];
    const float* bu   = (const float*)d_in[7];
    const float* Wo   = (const float*)d_in[8];
    const float* bo   = (const float*)d_in[9];
    const float* Wt   = (const float*)d_in[10];
    const float* bt   = (const float*)d_in[11];
    float* out = (float*)d_out;

    precompute_kernel<<<SEQ / TCHUNK, 256>>>(sent, emb, Wf, bf, Wi, bi, Wu, bu, Wo, bo);
    scan_kernel<<<1, 32>>>(Wf, Wi, Wu, Wo);
    logits_kernel<<<SEQ, 32>>>(Wt, bt, out);
}